// round 1
// baseline (speedup 1.0000x reference)
#include <cuda_runtime.h>

#define NN 8192        // nodes
#define NW 256         // mask words per row (8192/32)
#define DIM 128

// exp(-ALPHA*k), ALPHA=2
#define F1 0.13533528323661270f
#define F2 0.018315638888734179f
#define F3 0.0024787521766663585f

// ---------------- scratch (static device globals; no allocation) ----------------
__device__ unsigned g_adj[NN * NW];   // 8 MB  adjacency bitmask, row-major (out-edges)
__device__ unsigned g_P2[NN * NW];    // 8 MB  bool(adj^2)
__device__ unsigned g_P3[NN * NW];    // 8 MB  bool(adj^3)
__device__ float    g_h1[NN * DIM];   // 4 MB  MLP activations (ping)
__device__ float    g_h2[NN * DIM];   // 4 MB  MLP activations (pong)
__device__ float    g_ang[NN];        // angles
__device__ float    g_s1[NN];         // hop-1 step (atomic accumulate)
__device__ float    g_s2[NN];         // step after hop 2
__device__ float    g_enh2[NN];       // enhanced after hop 2
__device__ float    g_lut[(NN / 8) * 256];  // 1 MB byte-LUT of enh2 partial sums

// ---------------- init ----------------
__global__ void zero_kernel() {
    int i = blockIdx.x * blockDim.x + threadIdx.x;
    int stride = gridDim.x * blockDim.x;
    for (int k = i; k < NN * NW; k += stride) g_adj[k] = 0u;
    if (i < NN) g_s1[i] = 0.0f;
}

// ---------------- adjacency bitmask from edge list ----------------
__global__ void build_adj(const int* __restrict__ ei, int E) {
    int t = blockIdx.x * blockDim.x + threadIdx.x;
    if (t >= E) return;
    int r = ei[t];
    int c = ei[E + t];
    atomicOr(&g_adj[r * NW + (c >> 5)], 1u << (c & 31));
}

// ---------------- one boolean hop: dst[i] = OR over set bits j of nbrs[i] of src[j] -------
// block = one row, 64 threads (each owns 4 output words as uint4)
__global__ void build_hop(const unsigned* __restrict__ nbrs,
                          const unsigned* __restrict__ src,
                          unsigned* __restrict__ dst) {
    __shared__ int cnt;
    __shared__ short nlist[1024];
    int i = blockIdx.x;
    int t = threadIdx.x;  // 0..63
    if (t == 0) cnt = 0;
    __syncthreads();

    uint4 w4 = ((const uint4*)(nbrs + i * NW))[t];
    unsigned ws[4] = {w4.x, w4.y, w4.z, w4.w};
#pragma unroll
    for (int q = 0; q < 4; q++) {
        unsigned w = ws[q];
        int base = (t * 4 + q) * 32;
        while (w) {
            int b = __ffs((int)w) - 1;
            w &= (w - 1);
            int idx = atomicAdd(&cnt, 1);
            if (idx < 1024) nlist[idx] = (short)(base + b);
        }
    }
    __syncthreads();
    int n = cnt < 1024 ? cnt : 1024;
    uint4 acc = make_uint4(0u, 0u, 0u, 0u);
    for (int k = 0; k < n; k++) {
        int j = nlist[k];
        uint4 v = ((const uint4*)(src + j * NW))[t];
        acc.x |= v.x; acc.y |= v.y; acc.z |= v.z; acc.w |= v.w;
    }
    ((uint4*)(dst + i * NW))[t] = acc;
}

// ---------------- fp32 GEMM  C[8192,128] = relu(A[8192,128] @ B[128,128]) ----------------
// 64-row tile per block, full N=128 and K=128 staged in smem. 256 threads, 4x8 microtile.
extern __shared__ float smem_gemm[];
__global__ void __launch_bounds__(256) gemm_relu(const float* __restrict__ A,
                                                 const float* __restrict__ B,
                                                 float* __restrict__ C) {
    float* As = smem_gemm;              // [128][68]  As[k][row] (transposed, padded)
    float* Bs = smem_gemm + 128 * 68;   // [128][128] Bs[k][col]
    int tid = threadIdx.x;
    int row0 = blockIdx.x * 64;

    {   // load A tile (transposed into smem)
        int r = tid >> 2;               // 0..63
        int k0 = (tid & 3) * 32;
        const float4* src = (const float4*)(A + (row0 + r) * DIM + k0);
#pragma unroll
        for (int i = 0; i < 8; i++) {
            float4 v = src[i];
            int k = k0 + i * 4;
            As[(k + 0) * 68 + r] = v.x;
            As[(k + 1) * 68 + r] = v.y;
            As[(k + 2) * 68 + r] = v.z;
            As[(k + 3) * 68 + r] = v.w;
        }
        // load B (full 128x128)
        const float4* bs = (const float4*)B;
        float4* bd = (float4*)Bs;
#pragma unroll
        for (int i = 0; i < 16; i++) bd[tid + i * 256] = bs[tid + i * 256];
    }
    __syncthreads();

    int tx = tid & 15, ty = tid >> 4;
    float acc[4][8];
#pragma unroll
    for (int r = 0; r < 4; r++)
#pragma unroll
        for (int c = 0; c < 8; c++) acc[r][c] = 0.0f;

#pragma unroll 4
    for (int k = 0; k < 128; k++) {
        float4 a  = *(const float4*)&As[k * 68 + ty * 4];
        float4 b0 = *(const float4*)&Bs[k * 128 + tx * 4];
        float4 b1 = *(const float4*)&Bs[k * 128 + 64 + tx * 4];
        float av[4] = {a.x, a.y, a.z, a.w};
        float bv[8] = {b0.x, b0.y, b0.z, b0.w, b1.x, b1.y, b1.z, b1.w};
#pragma unroll
        for (int r = 0; r < 4; r++)
#pragma unroll
            for (int c = 0; c < 8; c++) acc[r][c] += av[r] * bv[c];
    }

#pragma unroll
    for (int r = 0; r < 4; r++) {
        int row = row0 + ty * 4 + r;
        float4 o0, o1;
        o0.x = fmaxf(acc[r][0], 0.0f); o0.y = fmaxf(acc[r][1], 0.0f);
        o0.z = fmaxf(acc[r][2], 0.0f); o0.w = fmaxf(acc[r][3], 0.0f);
        o1.x = fmaxf(acc[r][4], 0.0f); o1.y = fmaxf(acc[r][5], 0.0f);
        o1.z = fmaxf(acc[r][6], 0.0f); o1.w = fmaxf(acc[r][7], 0.0f);
        *(float4*)(C + row * DIM + tx * 4)      = o0;
        *(float4*)(C + row * DIM + 64 + tx * 4) = o1;
    }
}

// ---------------- final layer: angles = H @ W3 (128 -> 1), one warp per row ------------
__global__ void matvec_w3(const float* __restrict__ H, const float* __restrict__ w) {
    int gw = (blockIdx.x * blockDim.x + threadIdx.x) >> 5;
    int lane = threadIdx.x & 31;
    if (gw >= NN) return;
    const float* hr = H + gw * DIM;
    float s = hr[lane] * w[lane] + hr[lane + 32] * w[lane + 32]
            + hr[lane + 64] * w[lane + 64] + hr[lane + 96] * w[lane + 96];
#pragma unroll
    for (int o = 16; o; o >>= 1) s += __shfl_xor_sync(0xffffffffu, s, o);
    if (lane == 0) g_ang[gw] = s;
}

// ---------------- hop-1 scatter over raw edge list (duplicates counted) ----------------
__global__ void scatter1(const int* __restrict__ ei, int E) {
    int t = blockIdx.x * blockDim.x + threadIdx.x;
    if (t >= E) return;
    atomicAdd(&g_s1[ei[t]], F1 * g_ang[ei[E + t]]);
}

// ---------------- hop 2: y2 = P2 @ enh1 (sparse mask, popcount-driven, smem vector) -----
// 256 threads, 32 rows per block (4 rows per warp)
__global__ void hop2_kernel() {
    __shared__ float v[NN];   // 32 KB: enh1 = angles + s1
    int tid = threadIdx.x;
    for (int i = tid; i < NN; i += 256) v[i] = g_ang[i] + g_s1[i];
    __syncthreads();
    int lane = tid & 31, warp = tid >> 5;
    for (int rr = 0; rr < 4; rr++) {
        int row = blockIdx.x * 32 + warp * 4 + rr;
        const unsigned* m = g_P2 + row * NW;
        float s = 0.0f;
#pragma unroll
        for (int t = 0; t < 8; t++) {
            int wi = lane + 32 * t;
            unsigned w = m[wi];
            const float* vb = v + wi * 32;
            while (w) {
                int b = __ffs((int)w) - 1;
                w &= (w - 1);
                s += vb[b];
            }
        }
#pragma unroll
        for (int o = 16; o; o >>= 1) s += __shfl_xor_sync(0xffffffffu, s, o);
        if (lane == 0) {
            float e1  = v[row];             // angles + s1
            float st2 = g_s1[row] + F2 * s; // step after hop 2
            g_s2[row]   = st2;
            g_enh2[row] = e1 + st2;
        }
    }
}

// ---------------- byte-LUT of enh2 partial sums: lut[g*256+m] = sum over bits of m ------
__global__ void build_lut() {
    __shared__ float v[8];
    int g = blockIdx.x;
    int m = threadIdx.x;
    if (m < 8) v[m] = g_enh2[g * 8 + m];
    __syncthreads();
    float s = 0.0f;
#pragma unroll
    for (int b = 0; b < 8; b++) s += ((m >> b) & 1) ? v[b] : 0.0f;
    g_lut[g * 256 + m] = s;
}

// ---------------- hop 3: y3 = P3 @ enh2 via byte-LUT; writes final output --------------
__global__ void hop3_kernel(float* __restrict__ out) {
    int tid = threadIdx.x, lane = tid & 31, warp = tid >> 5;
    for (int rr = 0; rr < 4; rr++) {
        int row = blockIdx.x * 32 + warp * 4 + rr;
        const unsigned* m = g_P3 + row * NW;
        float s = 0.0f;
#pragma unroll
        for (int t = 0; t < 8; t++) {
            int wi = lane + 32 * t;
            unsigned w = m[wi];
            const float* L = g_lut + wi * 1024;   // 4 byte-groups per word
            s += L[w & 255u];
            s += L[256 + ((w >> 8) & 255u)];
            s += L[512 + ((w >> 16) & 255u)];
            s += L[768 + (w >> 24)];
        }
#pragma unroll
        for (int o = 16; o; o >>= 1) s += __shfl_xor_sync(0xffffffffu, s, o);
        if (lane == 0) out[row] = g_enh2[row] + g_s2[row] + F3 * s;
    }
}

// ---------------- launch ----------------
extern "C" void kernel_launch(void* const* d_in, const int* in_sizes, int n_in,
                              void* d_out, int out_size) {
    const float* coeffs = (const float*)d_in[0];
    const float* W0 = (const float*)d_in[1];
    const float* W1 = (const float*)d_in[2];
    const float* W2 = (const float*)d_in[3];
    const float* W3 = (const float*)d_in[4];
    const int*   ei = (const int*)d_in[5];
    int E = in_sizes[5] / 2;
    float* out = (float*)d_out;

    float *h1, *h2;
    unsigned *adj, *P2, *P3;
    cudaGetSymbolAddress((void**)&h1, g_h1);
    cudaGetSymbolAddress((void**)&h2, g_h2);
    cudaGetSymbolAddress((void**)&adj, g_adj);
    cudaGetSymbolAddress((void**)&P2, g_P2);
    cudaGetSymbolAddress((void**)&P3, g_P3);

    const int gemm_smem = (128 * 68 + 128 * 128) * 4;  // ~100 KB
    cudaFuncSetAttribute(gemm_relu, cudaFuncAttributeMaxDynamicSharedMemorySize, gemm_smem);

    zero_kernel<<<2048, 256>>>();
    build_adj<<<(E + 255) / 256, 256>>>(ei, E);
    build_hop<<<NN, 64>>>(adj, adj, P2);   // P2 = bool(adj^2)
    build_hop<<<NN, 64>>>(adj, P2, P3);    // P3 = bool(adj^3)

    gemm_relu<<<NN / 64, 256, gemm_smem>>>(coeffs, W0, h1);
    gemm_relu<<<NN / 64, 256, gemm_smem>>>(h1, W1, h2);
    gemm_relu<<<NN / 64, 256, gemm_smem>>>(h2, W2, h1);
    matvec_w3<<<NN / 8, 256>>>(h1, W3);

    scatter1<<<(E + 255) / 256, 256>>>(ei, E);
    hop2_kernel<<<NN / 32, 256>>>();
    build_lut<<<NN / 8, 256>>>();
    hop3_kernel<<<NN / 32, 256>>>(out);
}

// round 3
// speedup vs baseline: 1.2904x; 1.2904x over previous
#include <cuda_runtime.h>
#include <cuda_bf16.h>
#include <cstdint>

#define NN 8192        // nodes
#define NW 256         // mask words per row (8192/32)
#define DIM 128
#define LDW 136        // padded bf16 row stride (272 B) -> conflict-free ldmatrix

// exp(-ALPHA*k), ALPHA=2
#define F1 0.13533528323661270f
#define F2 0.018315638888734179f
#define F3 0.0024787521766663585f

// ---------------- scratch (static device globals; no allocation) ----------------
__device__ unsigned g_adj[NN * NW];   // 8 MB adjacency bitmask
__device__ unsigned g_P2[NN * NW];    // 8 MB bool(adj^2)
__device__ float    g_ang[NN];
__device__ float    g_s1[NN];
__device__ float    g_enh1[NN];
__device__ float    g_s2[NN];
__device__ float    g_enh2[NN];
__device__ float    g_lut[(NN / 8) * 256];           // 1 MB byte-LUT of enh2
__device__ __align__(16) __nv_bfloat16 g_Whi[3][DIM * LDW];  // pre-split W, [n][k] padded
__device__ __align__(16) __nv_bfloat16 g_Wlo[3][DIM * LDW];

// ================= PTX helpers (family-agnostic ISA only) =================
__device__ __forceinline__ uint32_t smem_u32(const void* p) {
    uint32_t a;
    asm("{ .reg .u64 t; cvta.to.shared.u64 t, %1; cvt.u32.u64 %0, t; }" : "=r"(a) : "l"(p));
    return a;
}
__device__ __forceinline__ void ldm_x4(uint32_t* r, uint32_t addr) {
    asm volatile("ldmatrix.sync.aligned.m8n8.x4.shared.b16 {%0,%1,%2,%3}, [%4];"
                 : "=r"(r[0]), "=r"(r[1]), "=r"(r[2]), "=r"(r[3]) : "r"(addr));
}
__device__ __forceinline__ void mma_bf16(float* c, const uint32_t* a, uint32_t b0, uint32_t b1) {
    asm volatile(
        "mma.sync.aligned.m16n8k16.row.col.f32.bf16.bf16.f32 "
        "{%0,%1,%2,%3}, {%4,%5,%6,%7}, {%8,%9}, {%0,%1,%2,%3};"
        : "+f"(c[0]), "+f"(c[1]), "+f"(c[2]), "+f"(c[3])
        : "r"(a[0]), "r"(a[1]), "r"(a[2]), "r"(a[3]), "r"(b0), "r"(b1));
}

// ---------------- init ----------------
__global__ void zero_kernel() {
    int i = blockIdx.x * blockDim.x + threadIdx.x;
    int stride = gridDim.x * blockDim.x;
    for (int k = i; k < NN * NW; k += stride) g_adj[k] = 0u;
    if (i < NN) g_s1[i] = 0.0f;
}

__global__ void build_adj(const int* __restrict__ ei, int E) {
    int t = blockIdx.x * blockDim.x + threadIdx.x;
    if (t >= E) return;
    int r = ei[t];
    int c = ei[E + t];
    atomicOr(&g_adj[r * NW + (c >> 5)], 1u << (c & 31));
}

// ---------------- W pre-split into padded [n][k] bf16 hi/lo images ----------------
__global__ void split_W(const float* __restrict__ W0, const float* __restrict__ W1,
                        const float* __restrict__ W2) {
    int idx = blockIdx.x * blockDim.x + threadIdx.x;    // 0..49151
    if (idx >= 3 * DIM * DIM) return;
    int l = idx >> 14;
    int e = idx & 16383;
    int k = e >> 7, n = e & 127;
    const float* W = (l == 0) ? W0 : ((l == 1) ? W1 : W2);
    float w = W[e];  // W[k][n]
    __nv_bfloat16 hi = __float2bfloat16(w);
    __nv_bfloat16 lo = __float2bfloat16(w - __bfloat162float(hi));
    g_Whi[l][n * LDW + k] = hi;   // B operand stored [n][k] (col-major k x n)
    g_Wlo[l][n * LDW + k] = lo;
}

// ---------------- fused MLP: 3x (128x128 GEMM + relu) + W3 matvec ----------------
// CTA = 64 rows, 256 threads (8 warps: wm = w&3 -> 16-row tile, wn = w>>2 -> 64-col half)
#define ROWS_CTA 64
#define SM_W3   0                         // 128 f32
#define SM_ROWS 512                       // 64 f32 row accumulators
#define SM_AHI  768
#define SM_ALO  (SM_AHI + ROWS_CTA * LDW * 2)     // +17408
#define SM_WHI  (SM_ALO + ROWS_CTA * LDW * 2)
#define SM_WLO  (SM_WHI + DIM * LDW * 2)          // +34816
#define SM_MLP  (SM_WLO + DIM * LDW * 2)          // ~105 KB

__device__ __forceinline__ void store_split_u32(char* smem, int base, int row, int col,
                                                float x0, float x1) {
    __nv_bfloat16 h0 = __float2bfloat16(x0);
    __nv_bfloat16 h1 = __float2bfloat16(x1);
    *(uint32_t*)(smem + base + (row * LDW + col) * 2) =
        ((uint32_t)__bfloat16_as_ushort(h1) << 16) | (uint32_t)__bfloat16_as_ushort(h0);
}

__device__ __forceinline__ void copy_w_layer(char* smem, int l) {
    const uint4* sh = (const uint4*)g_Whi[l];
    const uint4* sl = (const uint4*)g_Wlo[l];
    uint4* dh = (uint4*)(smem + SM_WHI);
    uint4* dl = (uint4*)(smem + SM_WLO);
#pragma unroll 2
    for (int i = threadIdx.x; i < DIM * LDW * 2 / 16; i += 256) { dh[i] = sh[i]; dl[i] = sl[i]; }
}

__global__ void __launch_bounds__(256, 1)
mlp_kernel(const float* __restrict__ coeffs, const float* __restrict__ W3) {
    extern __shared__ char smem[];
    uint32_t sb = smem_u32(smem);
    int t = threadIdx.x;
    int w = t >> 5, lane = t & 31;
    int wm = w & 3, wn = w >> 2;
    int row0 = blockIdx.x * ROWS_CTA;

    if (t < 128) ((float*)(smem + SM_W3))[t] = W3[t];
    if (t < ROWS_CTA) ((float*)(smem + SM_ROWS))[t] = 0.0f;

    // load + split this CTA's A tile: thread t -> row t/4, k-section (t&3)*32
    {
        int r = t >> 2, k0 = (t & 3) * 32;
        const float4* src = (const float4*)(coeffs + (size_t)(row0 + r) * DIM + k0);
#pragma unroll
        for (int i = 0; i < 8; i++) {
            float4 v = src[i];
            int c = k0 + i * 4;
            __nv_bfloat16 h0 = __float2bfloat16(v.x), h1 = __float2bfloat16(v.y);
            __nv_bfloat16 h2 = __float2bfloat16(v.z), h3 = __float2bfloat16(v.w);
            store_split_u32(smem, SM_AHI, r, c,     v.x, v.y);
            store_split_u32(smem, SM_AHI, r, c + 2, v.z, v.w);
            store_split_u32(smem, SM_ALO, r, c,
                            v.x - __bfloat162float(h0), v.y - __bfloat162float(h1));
            store_split_u32(smem, SM_ALO, r, c + 2,
                            v.z - __bfloat162float(h2), v.w - __bfloat162float(h3));
        }
    }
    copy_w_layer(smem, 0);
    __syncthreads();

    const float* W3s = (const float*)(smem + SM_W3);
    float* rows = (float*)(smem + SM_ROWS);
    int rowA = wm * 16;           // this warp's 16-row tile
    int nbase0 = wn * 64;         // this warp's 64-col half

    for (int layer = 0; layer < 3; layer++) {
        float acc[8][4];
#pragma unroll
        for (int nt = 0; nt < 8; nt++)
#pragma unroll
            for (int q = 0; q < 4; q++) acc[nt][q] = 0.0f;

#pragma unroll 2
        for (int k = 0; k < 8; k++) {
            // A fragments (hi, lo): m16k16 at (rowA, k*16)
            uint32_t ahi[4], alo[4];
            uint32_t aoff = ((rowA + (lane & 15)) * LDW + k * 16 + ((lane >> 4) * 8)) * 2;
            ldm_x4(ahi, sb + SM_AHI + aoff);
            ldm_x4(alo, sb + SM_ALO + aoff);
#pragma unroll
            for (int np = 0; np < 4; np++) {       // n-tile pairs (16 cols)
                int nbase = nbase0 + np * 16;
                uint32_t boff = ((nbase + ((lane >> 3) & 1) * 8 + (lane & 7)) * LDW
                                 + k * 16 + ((lane >> 4) * 8)) * 2;
                uint32_t bhi[4], blo[4];
                ldm_x4(bhi, sb + SM_WHI + boff);
                ldm_x4(blo, sb + SM_WLO + boff);
                uint32_t h0a = bhi[0], h0b = bhi[2], h1a = bhi[1], h1b = bhi[3];
                uint32_t l0a = blo[0], l0b = blo[2], l1a = blo[1], l1b = blo[3];
                mma_bf16(acc[np * 2],     ahi, h0a, h0b);
                mma_bf16(acc[np * 2],     ahi, l0a, l0b);
                mma_bf16(acc[np * 2],     alo, h0a, h0b);
                mma_bf16(acc[np * 2 + 1], ahi, h1a, h1b);
                mma_bf16(acc[np * 2 + 1], ahi, l1a, l1b);
                mma_bf16(acc[np * 2 + 1], alo, h1a, h1b);
            }
        }
        __syncthreads();   // everyone done reading A (and W) for this layer

        if (layer < 2) {
            // relu + split back into Ahi/Alo; fetch next layer's W
            int rw = rowA + (lane >> 2);
#pragma unroll
            for (int nt = 0; nt < 8; nt++) {
                int col = nbase0 + nt * 8 + (lane & 3) * 2;
                float f0 = fmaxf(acc[nt][0], 0.0f), f1 = fmaxf(acc[nt][1], 0.0f);
                float f2 = fmaxf(acc[nt][2], 0.0f), f3 = fmaxf(acc[nt][3], 0.0f);
                __nv_bfloat16 h0 = __float2bfloat16(f0), h1 = __float2bfloat16(f1);
                __nv_bfloat16 h2 = __float2bfloat16(f2), h3 = __float2bfloat16(f3);
                store_split_u32(smem, SM_AHI, rw,     col, f0, f1);
                store_split_u32(smem, SM_AHI, rw + 8, col, f2, f3);
                store_split_u32(smem, SM_ALO, rw,     col,
                                f0 - __bfloat162float(h0), f1 - __bfloat162float(h1));
                store_split_u32(smem, SM_ALO, rw + 8, col,
                                f2 - __bfloat162float(h2), f3 - __bfloat162float(h3));
            }
            copy_w_layer(smem, layer + 1);
            __syncthreads();
        } else {
            // final: dot rows of relu(H) with W3, reduce into smem rows[]
            float p0 = 0.0f, p1 = 0.0f;
#pragma unroll
            for (int nt = 0; nt < 8; nt++) {
                int col = nbase0 + nt * 8 + (lane & 3) * 2;
                p0 += fmaxf(acc[nt][0], 0.0f) * W3s[col] + fmaxf(acc[nt][1], 0.0f) * W3s[col + 1];
                p1 += fmaxf(acc[nt][2], 0.0f) * W3s[col] + fmaxf(acc[nt][3], 0.0f) * W3s[col + 1];
            }
            p0 += __shfl_xor_sync(0xffffffffu, p0, 1);
            p0 += __shfl_xor_sync(0xffffffffu, p0, 2);
            p1 += __shfl_xor_sync(0xffffffffu, p1, 1);
            p1 += __shfl_xor_sync(0xffffffffu, p1, 2);
            if ((lane & 3) == 0) {
                atomicAdd(&rows[rowA + (lane >> 2)], p0);
                atomicAdd(&rows[rowA + (lane >> 2) + 8], p1);
            }
            __syncthreads();
            if (t < ROWS_CTA) g_ang[row0 + t] = rows[t];
        }
    }
}

// ---------------- hop-1 scatter over raw edge list (duplicates counted) ----------------
__global__ void scatter1(const int* __restrict__ ei, int E) {
    int t = blockIdx.x * blockDim.x + threadIdx.x;
    if (t >= E) return;
    atomicAdd(&g_s1[ei[t]], F1 * g_ang[ei[E + t]]);
}

__global__ void enh1_kernel() {
    int i = blockIdx.x * blockDim.x + threadIdx.x;
    if (i < NN) g_enh1[i] = g_ang[i] + g_s1[i];
}

// ---------------- k1: build P2 row + dot(P2row, enh1) fused ----------------
__global__ void k1_p2(void) {
    __shared__ int cnt;
    __shared__ short nlist[1024];
    __shared__ float red[2];
    int i = blockIdx.x;
    int t = threadIdx.x;  // 0..63
    if (t == 0) cnt = 0;
    __syncthreads();

    uint4 w4 = ((const uint4*)(g_adj + i * NW))[t];
    {
        unsigned ws[4] = {w4.x, w4.y, w4.z, w4.w};
#pragma unroll
        for (int q = 0; q < 4; q++) {
            unsigned w = ws[q];
            int base = (t * 4 + q) * 32;
            while (w) {
                int b = __ffs((int)w) - 1;
                w &= (w - 1);
                int idx = atomicAdd(&cnt, 1);
                if (idx < 1024) nlist[idx] = (short)(base + b);
            }
        }
    }
    __syncthreads();
    int n = cnt < 1024 ? cnt : 1024;
    uint4 acc = make_uint4(0u, 0u, 0u, 0u);
    int k = 0;
    for (; k + 2 <= n; k += 2) {
        int j0 = nlist[k], j1 = nlist[k + 1];
        uint4 v0 = ((const uint4*)(g_adj + j0 * NW))[t];
        uint4 v1 = ((const uint4*)(g_adj + j1 * NW))[t];
        acc.x |= v0.x | v1.x; acc.y |= v0.y | v1.y;
        acc.z |= v0.z | v1.z; acc.w |= v0.w | v1.w;
    }
    if (k < n) {
        uint4 v = ((const uint4*)(g_adj + nlist[k] * NW))[t];
        acc.x |= v.x; acc.y |= v.y; acc.z |= v.z; acc.w |= v.w;
    }
    ((uint4*)(g_P2 + i * NW))[t] = acc;

    // dot P2row . enh1 (ffs; sparse)
    float s = 0.0f;
    {
        unsigned aw[4] = {acc.x, acc.y, acc.z, acc.w};
#pragma unroll
        for (int q = 0; q < 4; q++) {
            unsigned w = aw[q];
            const float* vb = g_enh1 + (t * 4 + q) * 32;
            while (w) {
                int b = __ffs((int)w) - 1;
                w &= (w - 1);
                s += __ldg(&vb[b]);
            }
        }
    }
#pragma unroll
    for (int o = 16; o; o >>= 1) s += __shfl_xor_sync(0xffffffffu, s, o);
    int lane = t & 31, wp = t >> 5;
    if (lane == 0) red[wp] = s;
    __syncthreads();
    if (t == 0) {
        float y2 = red[0] + red[1];
        float st2 = g_s1[i] + F2 * y2;
        g_s2[i] = st2;
        g_enh2[i] = g_enh1[i] + st2;
    }
}

// ---------------- byte-LUT of enh2 partial sums ----------------
__global__ void build_lut() {
    __shared__ float v[8];
    int g = blockIdx.x;
    int m = threadIdx.x;
    if (m < 8) v[m] = g_enh2[g * 8 + m];
    __syncthreads();
    float s = 0.0f;
#pragma unroll
    for (int b = 0; b < 8; b++) s += ((m >> b) & 1) ? v[b] : 0.0f;
    g_lut[g * 256 + m] = s;
}

// ---------------- k2: build P3 row IN REGISTERS + LUT dot -> final out ----------------
__global__ void k2_p3(float* __restrict__ out) {
    __shared__ int cnt;
    __shared__ short nlist[1024];
    __shared__ float red[2];
    int i = blockIdx.x;
    int t = threadIdx.x;  // 0..63
    if (t == 0) cnt = 0;
    __syncthreads();

    uint4 w4 = ((const uint4*)(g_adj + i * NW))[t];
    {
        unsigned ws[4] = {w4.x, w4.y, w4.z, w4.w};
#pragma unroll
        for (int q = 0; q < 4; q++) {
            unsigned w = ws[q];
            int base = (t * 4 + q) * 32;
            while (w) {
                int b = __ffs((int)w) - 1;
                w &= (w - 1);
                int idx = atomicAdd(&cnt, 1);
                if (idx < 1024) nlist[idx] = (short)(base + b);
            }
        }
    }
    __syncthreads();
    int n = cnt < 1024 ? cnt : 1024;
    uint4 acc = make_uint4(0u, 0u, 0u, 0u);
    int k = 0;
    for (; k + 2 <= n; k += 2) {
        int j0 = nlist[k], j1 = nlist[k + 1];
        uint4 v0 = ((const uint4*)(g_P2 + j0 * NW))[t];
        uint4 v1 = ((const uint4*)(g_P2 + j1 * NW))[t];
        acc.x |= v0.x | v1.x; acc.y |= v0.y | v1.y;
        acc.z |= v0.z | v1.z; acc.w |= v0.w | v1.w;
    }
    if (k < n) {
        uint4 v = ((const uint4*)(g_P2 + nlist[k] * NW))[t];
        acc.x |= v.x; acc.y |= v.y; acc.z |= v.z; acc.w |= v.w;
    }

    // dot P3row . enh2 via byte-LUT (~40% density)
    float s = 0.0f;
    {
        unsigned aw[4] = {acc.x, acc.y, acc.z, acc.w};
#pragma unroll
        for (int q = 0; q < 4; q++) {
            unsigned w = aw[q];
            const float* L = g_lut + (t * 4 + q) * 1024;
            s += L[w & 255u];
            s += L[256 + ((w >> 8) & 255u)];
            s += L[512 + ((w >> 16) & 255u)];
            s += L[768 + (w >> 24)];
        }
    }
#pragma unroll
    for (int o = 16; o; o >>= 1) s += __shfl_xor_sync(0xffffffffu, s, o);
    int lane = t & 31, wp = t >> 5;
    if (lane == 0) red[wp] = s;
    __syncthreads();
    if (t == 0) out[i] = g_enh2[i] + g_s2[i] + F3 * (red[0] + red[1]);
}

// ---------------- launch ----------------
extern "C" void kernel_launch(void* const* d_in, const int* in_sizes, int n_in,
                              void* d_out, int out_size) {
    const float* coeffs = (const float*)d_in[0];
    const float* W0 = (const float*)d_in[1];
    const float* W1 = (const float*)d_in[2];
    const float* W2 = (const float*)d_in[3];
    const float* W3 = (const float*)d_in[4];
    const int*   ei = (const int*)d_in[5];
    int E = in_sizes[5] / 2;
    float* out = (float*)d_out;

    cudaFuncSetAttribute(mlp_kernel, cudaFuncAttributeMaxDynamicSharedMemorySize, SM_MLP);

    zero_kernel<<<2048, 256>>>();
    build_adj<<<(E + 255) / 256, 256>>>(ei, E);
    split_W<<<192, 256>>>(W0, W1, W2);
    mlp_kernel<<<NN / ROWS_CTA, 256, SM_MLP>>>(coeffs, W3);
    scatter1<<<(E + 255) / 256, 256>>>(ei, E);
    enh1_kernel<<<32, 256>>>();
    k1_p2<<<NN, 64>>>();
    build_lut<<<NN / 8, 256>>>();
    k2_p3<<<NN, 64>>>(out);
}